// round 11
// baseline (speedup 1.0000x reference)
#include <cuda_runtime.h>
#include <math.h>

#define Sdim 2048
#define Edim 512
#define WIN  11
#define Fdim 5632            // WIN * Edim
#define NTH  256

// Packed dual-fp32 FMA: a.{x,y} += {xlo,xhi} * w   (w broadcast to both lanes)
__device__ __forceinline__ void ffma2(float2& a, float xlo, float xhi, float w) {
    asm("{\n\t.reg .b64 X, Wd, A;\n\t"
        "mov.b64 X, {%2, %3};\n\t"
        "mov.b64 Wd, {%4, %4};\n\t"
        "mov.b64 A, {%0, %1};\n\t"
        "fma.rn.f32x2 A, X, Wd, A;\n\t"
        "mov.b64 {%0, %1}, A;\n\t}"
        : "+f"(a.x), "+f"(a.y) : "f"(xlo), "f"(xhi), "f"(w));
}

__device__ __forceinline__ float tanh_fast(float v) {
    float r;
    asm("tanh.approx.f32 %0, %1;" : "=f"(r) : "f"(v));
    return r;
}

__global__ __launch_bounds__(NTH, 3)
void winattn_kernel(const float* __restrict__ x,
                    const float* __restrict__ W,
                    const float* __restrict__ bias,
                    float* __restrict__ out) {
    __shared__ float2 red[8][22];      // per-warp partials (2 pairs x 11 w)
    __shared__ float2 gates[22];       // gates for this CTA's 4 batches

    const int s   = blockIdx.x >> 1;
    const int b0  = (blockIdx.x & 1) * 4;   // batches b0..b0+3
    const int tid = threadIdx.x;
    const int ex  = 2 * tid;                // float2 slot within e (0..510)

    const size_t bst = (size_t)Sdim * Edim;
    const float* Wb = W + (size_t)s * (WIN * Fdim) + ex;
    const float* x0 = x + (size_t)(b0    ) * bst + ex;
    const float* x1 = x + (size_t)(b0 + 1) * bst + ex;
    const float* x2 = x + (size_t)(b0 + 2) * bst + ex;
    const float* x3 = x + (size_t)(b0 + 3) * bst + ex;
    const bool interior = (s >= 5) && (s <= Sdim - 6);

    // ---------------- Stage A: full-f gate dots for 4 batches --------------
    float2 acc[2][WIN];                // pair p: (batch b0+2p, b0+2p+1)
    #pragma unroll
    for (int p = 0; p < 2; p++)
        #pragma unroll
        for (int w = 0; w < WIN; w++)
            acc[p][w] = make_float2(0.f, 0.f);

    if (interior) {
        const int base = (s - 5) * Edim;
        #pragma unroll
        for (int i = 0; i < WIN; i++) {
            float2 w2[WIN];
            #pragma unroll
            for (int w = 0; w < WIN; w++)
                w2[w] = *(const float2*)(Wb + (size_t)w * Fdim + i * Edim);
            float2 xv0 = *(const float2*)(x0 + base + i * Edim);
            float2 xv1 = *(const float2*)(x1 + base + i * Edim);
            float2 xv2 = *(const float2*)(x2 + base + i * Edim);
            float2 xv3 = *(const float2*)(x3 + base + i * Edim);
            #pragma unroll
            for (int w = 0; w < WIN; w++) {
                ffma2(acc[0][w], xv0.x, xv1.x, w2[w].x);
                ffma2(acc[0][w], xv0.y, xv1.y, w2[w].y);
                ffma2(acc[1][w], xv2.x, xv3.x, w2[w].x);
                ffma2(acc[1][w], xv2.y, xv3.y, w2[w].y);
            }
        }
    } else {
        for (int i = 0; i < WIN; i++) {
            int row = s + i - 5;
            if ((unsigned)row >= (unsigned)Sdim) continue;
            float2 w2[WIN];
            #pragma unroll
            for (int w = 0; w < WIN; w++)
                w2[w] = *(const float2*)(Wb + (size_t)w * Fdim + i * Edim);
            const size_t ro = (size_t)row * Edim;
            float2 xv0 = *(const float2*)(x0 + ro);
            float2 xv1 = *(const float2*)(x1 + ro);
            float2 xv2 = *(const float2*)(x2 + ro);
            float2 xv3 = *(const float2*)(x3 + ro);
            #pragma unroll
            for (int w = 0; w < WIN; w++) {
                ffma2(acc[0][w], xv0.x, xv1.x, w2[w].x);
                ffma2(acc[0][w], xv0.y, xv1.y, w2[w].y);
                ffma2(acc[1][w], xv2.x, xv3.x, w2[w].x);
                ffma2(acc[1][w], xv2.y, xv3.y, w2[w].y);
            }
        }
    }

    // ---------------- reduce: warp shfl, then 8 warps via smem -------------
    float* af = (float*)acc;           // 44 floats
    #pragma unroll
    for (int off = 16; off > 0; off >>= 1) {
        #pragma unroll
        for (int i = 0; i < 44; i++)
            af[i] += __shfl_xor_sync(0xffffffffu, af[i], off);
    }
    const int lane = tid & 31, wrp = tid >> 5;
    if (lane == 0) {
        #pragma unroll
        for (int p = 0; p < 2; p++)
            #pragma unroll
            for (int w = 0; w < WIN; w++)
                red[wrp][p * WIN + w] = acc[p][w];
    }
    __syncthreads();

    if (tid < 22) {
        int p = tid / WIN;             // local pair 0..1
        int w = tid - p * WIN;
        float2 t = make_float2(0.f, 0.f);
        #pragma unroll
        for (int q = 0; q < 8; q++) {
            float2 v = red[q][tid];
            t.x += v.x;
            t.y += v.y;
        }
        float bb = bias[s * WIN + w];
        float2 gt;
        gt.x = 1.0f / (1.0f + expf(-(t.x + bb)));
        gt.y = 1.0f / (1.0f + expf(-(t.y + bb)));
        gates[tid] = gt;               // .x = batch b0+2p, .y = batch b0+2p+1
    }
    __syncthreads();

    // ---------------- Stage B: score + tanh (x via L1/L2) ------------------
    float2 a0 = {0.f, 0.f}, a1 = {0.f, 0.f}, a2 = {0.f, 0.f}, a3 = {0.f, 0.f};

    if (interior) {
        const int base = (s - 5) * Edim;
        #pragma unroll
        for (int w = 0; w < WIN; w++) {
            float2 xv0 = *(const float2*)(x0 + base + w * Edim);
            float2 xv1 = *(const float2*)(x1 + base + w * Edim);
            float2 xv2 = *(const float2*)(x2 + base + w * Edim);
            float2 xv3 = *(const float2*)(x3 + base + w * Edim);
            float2 g0 = gates[w];
            float2 g1 = gates[WIN + w];
            ffma2(a0, xv0.x, xv0.y, g0.x);
            ffma2(a1, xv1.x, xv1.y, g0.y);
            ffma2(a2, xv2.x, xv2.y, g1.x);
            ffma2(a3, xv3.x, xv3.y, g1.y);
        }
    } else {
        for (int w = 0; w < WIN; w++) {
            int row = s + w - 5;
            if ((unsigned)row >= (unsigned)Sdim) continue;
            const size_t ro = (size_t)row * Edim;
            float2 xv0 = *(const float2*)(x0 + ro);
            float2 xv1 = *(const float2*)(x1 + ro);
            float2 xv2 = *(const float2*)(x2 + ro);
            float2 xv3 = *(const float2*)(x3 + ro);
            float2 g0 = gates[w];
            float2 g1 = gates[WIN + w];
            ffma2(a0, xv0.x, xv0.y, g0.x);
            ffma2(a1, xv1.x, xv1.y, g0.y);
            ffma2(a2, xv2.x, xv2.y, g1.x);
            ffma2(a3, xv3.x, xv3.y, g1.y);
        }
    }

    const size_t ob = ((size_t)b0 * Sdim + s) * Edim + ex;
    *(float2*)(out + ob)           = make_float2(tanh_fast(a0.x), tanh_fast(a0.y));
    *(float2*)(out + ob + bst)     = make_float2(tanh_fast(a1.x), tanh_fast(a1.y));
    *(float2*)(out + ob + 2 * bst) = make_float2(tanh_fast(a2.x), tanh_fast(a2.y));
    *(float2*)(out + ob + 3 * bst) = make_float2(tanh_fast(a3.x), tanh_fast(a3.y));
}

extern "C" void kernel_launch(void* const* d_in, const int* in_sizes, int n_in,
                              void* d_out, int out_size) {
    const float* x  = (const float*)d_in[0];
    const float* W  = (const float*)d_in[1];
    const float* bv = (const float*)d_in[2];
    float* out = (float*)d_out;

    winattn_kernel<<<2 * Sdim, NTH>>>(x, W, bv, out);
}

// round 12
// speedup vs baseline: 1.4651x; 1.4651x over previous
#include <cuda_runtime.h>
#include <math.h>

#define Sdim 2048
#define Edim 512
#define WIN  11
#define Fdim 5632            // WIN * Edim
#define NTH  128

typedef unsigned long long u64;

// pack two floats into one 64-bit reg (f32x2 lanes)
__device__ __forceinline__ u64 pk(float lo, float hi) {
    u64 r;
    asm("mov.b64 %0, {%1, %2};" : "=l"(r) : "f"(lo), "f"(hi));
    return r;
}
// packed dual-fp32 FMA, accumulator stays packed: a += x * w (lane-wise)
__device__ __forceinline__ void fma2(u64& a, u64 x, u64 w) {
    asm("fma.rn.f32x2 %0, %1, %2, %0;" : "+l"(a) : "l"(x), "l"(w));
}
__device__ __forceinline__ float2 upk(u64 a) {
    float2 f;
    asm("mov.b64 {%0, %1}, %2;" : "=f"(f.x), "=f"(f.y) : "l"(a));
    return f;
}
__device__ __forceinline__ float tanh_fast(float v) {
    float r;
    asm("tanh.approx.f32 %0, %1;" : "=f"(r) : "f"(v));
    return r;
}

// one window-row chunk of stage A: 11 W float4 + 4 x float4 -> 88 packed FMA
__device__ __forceinline__ void stepA(const float* __restrict__ Wp, int ioff,
                                      float4 xv0, float4 xv1, float4 xv2, float4 xv3,
                                      u64 (&acc0)[WIN], u64 (&acc1)[WIN]) {
    float4 w4[WIN];
    #pragma unroll
    for (int w = 0; w < WIN; w++)
        w4[w] = *(const float4*)(Wp + (size_t)w * Fdim + ioff);

    // cross-batch packs: lanes = (batch even, batch odd)
    u64 p0x = pk(xv0.x, xv1.x), p0y = pk(xv0.y, xv1.y);
    u64 p0z = pk(xv0.z, xv1.z), p0w = pk(xv0.w, xv1.w);
    u64 p1x = pk(xv2.x, xv3.x), p1y = pk(xv2.y, xv3.y);
    u64 p1z = pk(xv2.z, xv3.z), p1w = pk(xv2.w, xv3.w);

    #pragma unroll
    for (int w = 0; w < WIN; w++) {
        u64 dx = pk(w4[w].x, w4[w].x);
        fma2(acc0[w], p0x, dx); fma2(acc1[w], p1x, dx);
        u64 dy = pk(w4[w].y, w4[w].y);
        fma2(acc0[w], p0y, dy); fma2(acc1[w], p1y, dy);
        u64 dz = pk(w4[w].z, w4[w].z);
        fma2(acc0[w], p0z, dz); fma2(acc1[w], p1z, dz);
        u64 dw = pk(w4[w].w, w4[w].w);
        fma2(acc0[w], p0w, dw); fma2(acc1[w], p1w, dw);
    }
}

__global__ __launch_bounds__(NTH, 4)
void winattn_kernel(const float* __restrict__ x,
                    const float* __restrict__ W,
                    const float* __restrict__ bias,
                    float* __restrict__ out) {
    __shared__ float2 red[4][22];      // per-warp partials (2 local pairs x 11 w)
    __shared__ float2 gates[22];       // gates for this CTA's 4 batches

    const int s   = blockIdx.x >> 1;
    const int b0  = (blockIdx.x & 1) * 4;   // batches b0..b0+3
    const int tid = threadIdx.x;
    const int ex  = 4 * tid;                // float4 slot within e (0..508)

    const size_t bst = (size_t)Sdim * Edim;
    const float* Wb  = W + (size_t)s * (WIN * Fdim) + ex;
    const float* xb  = x + (size_t)b0 * bst + ex;
    const float* xr0 = xb + (size_t)(s - 5) * Edim;   // window start row (batch b0)
    const float* xr2 = xr0 + 2 * bst;                 // same row, batch b0+2
    const bool interior = (s >= 5) && (s <= Sdim - 6);

    // ---------------- Stage A: full-f gate dots for 4 batches --------------
    u64 acc0[WIN], acc1[WIN];          // lanes: (b0,b0+1) and (b0+2,b0+3)
    #pragma unroll
    for (int w = 0; w < WIN; w++) { acc0[w] = 0ULL; acc1[w] = 0ULL; }

    if (interior) {
        #pragma unroll
        for (int i = 0; i < WIN; i++) {
            float4 xv0 = *(const float4*)(xr0 + i * Edim);
            float4 xv1 = *(const float4*)(xr0 + i * Edim + bst);
            float4 xv2 = *(const float4*)(xr2 + i * Edim);
            float4 xv3 = *(const float4*)(xr2 + i * Edim + bst);
            stepA(Wb, i * Edim, xv0, xv1, xv2, xv3, acc0, acc1);
        }
    } else {
        for (int i = 0; i < WIN; i++) {
            int row = s + i - 5;
            if ((unsigned)row >= (unsigned)Sdim) continue;
            const float* xr = xb + (size_t)row * Edim;
            float4 xv0 = *(const float4*)(xr);
            float4 xv1 = *(const float4*)(xr + bst);
            float4 xv2 = *(const float4*)(xr + 2 * bst);
            float4 xv3 = *(const float4*)(xr + 3 * bst);
            stepA(Wb, i * Edim, xv0, xv1, xv2, xv3, acc0, acc1);
        }
    }

    // unpack once for the reduction
    float af[44];
    #pragma unroll
    for (int w = 0; w < WIN; w++) {
        float2 t0 = upk(acc0[w]), t1 = upk(acc1[w]);
        af[w]          = t0.x;  af[WIN + w]      = t0.y;
        af[2 * WIN + w] = t1.x; af[3 * WIN + w]  = t1.y;
    }

    // ---------------- reduce: warp shfl, then 4 warps via smem -------------
    #pragma unroll
    for (int off = 16; off > 0; off >>= 1) {
        #pragma unroll
        for (int i = 0; i < 44; i++)
            af[i] += __shfl_xor_sync(0xffffffffu, af[i], off);
    }
    const int lane = tid & 31, wrp = tid >> 5;
    if (lane == 0) {
        #pragma unroll
        for (int w = 0; w < WIN; w++) {
            red[wrp][w]       = make_float2(af[w],          af[WIN + w]);
            red[wrp][WIN + w] = make_float2(af[2 * WIN + w], af[3 * WIN + w]);
        }
    }
    __syncthreads();

    if (tid < 22) {
        int p = tid / WIN;             // local pair 0..1
        int w = tid - p * WIN;
        float2 t = make_float2(0.f, 0.f);
        #pragma unroll
        for (int q = 0; q < 4; q++) {
            float2 v = red[q][tid];
            t.x += v.x;
            t.y += v.y;
        }
        float bb = bias[s * WIN + w];
        float2 gt;
        gt.x = 1.0f / (1.0f + expf(-(t.x + bb)));
        gt.y = 1.0f / (1.0f + expf(-(t.y + bb)));
        gates[tid] = gt;               // .x = batch b0+2p, .y = batch b0+2p+1
    }
    __syncthreads();

    // ---------------- Stage B: score + tanh (packed over e-pairs) ----------
    u64 a0l = 0, a0h = 0, a1l = 0, a1h = 0;   // per-batch, lanes = (e, e+1)
    u64 a2l = 0, a2h = 0, a3l = 0, a3h = 0;

    if (interior) {
        #pragma unroll
        for (int w = 0; w < WIN; w++) {
            ulonglong2 xv0 = *(const ulonglong2*)(xr0 + w * Edim);
            ulonglong2 xv1 = *(const ulonglong2*)(xr0 + w * Edim + bst);
            ulonglong2 xv2 = *(const ulonglong2*)(xr2 + w * Edim);
            ulonglong2 xv3 = *(const ulonglong2*)(xr2 + w * Edim + bst);
            float2 g0 = gates[w];
            float2 g1 = gates[WIN + w];
            u64 d0 = pk(g0.x, g0.x), d1 = pk(g0.y, g0.y);
            u64 d2 = pk(g1.x, g1.x), d3 = pk(g1.y, g1.y);
            fma2(a0l, xv0.x, d0); fma2(a0h, xv0.y, d0);
            fma2(a1l, xv1.x, d1); fma2(a1h, xv1.y, d1);
            fma2(a2l, xv2.x, d2); fma2(a2h, xv2.y, d2);
            fma2(a3l, xv3.x, d3); fma2(a3h, xv3.y, d3);
        }
    } else {
        for (int w = 0; w < WIN; w++) {
            int row = s + w - 5;
            if ((unsigned)row >= (unsigned)Sdim) continue;
            const float* xr = xb + (size_t)row * Edim;
            ulonglong2 xv0 = *(const ulonglong2*)(xr);
            ulonglong2 xv1 = *(const ulonglong2*)(xr + bst);
            ulonglong2 xv2 = *(const ulonglong2*)(xr + 2 * bst);
            ulonglong2 xv3 = *(const ulonglong2*)(xr + 3 * bst);
            float2 g0 = gates[w];
            float2 g1 = gates[WIN + w];
            u64 d0 = pk(g0.x, g0.x), d1 = pk(g0.y, g0.y);
            u64 d2 = pk(g1.x, g1.x), d3 = pk(g1.y, g1.y);
            fma2(a0l, xv0.x, d0); fma2(a0h, xv0.y, d0);
            fma2(a1l, xv1.x, d1); fma2(a1h, xv1.y, d1);
            fma2(a2l, xv2.x, d2); fma2(a2h, xv2.y, d2);
            fma2(a3l, xv3.x, d3); fma2(a3h, xv3.y, d3);
        }
    }

    {
        float2 l, h;
        float* op = out + ((size_t)b0 * Sdim + s) * Edim + ex;
        l = upk(a0l); h = upk(a0h);
        *(float4*)(op)           = make_float4(tanh_fast(l.x), tanh_fast(l.y), tanh_fast(h.x), tanh_fast(h.y));
        l = upk(a1l); h = upk(a1h);
        *(float4*)(op + bst)     = make_float4(tanh_fast(l.x), tanh_fast(l.y), tanh_fast(h.x), tanh_fast(h.y));
        l = upk(a2l); h = upk(a2h);
        *(float4*)(op + 2 * bst) = make_float4(tanh_fast(l.x), tanh_fast(l.y), tanh_fast(h.x), tanh_fast(h.y));
        l = upk(a3l); h = upk(a3h);
        *(float4*)(op + 3 * bst) = make_float4(tanh_fast(l.x), tanh_fast(l.y), tanh_fast(h.x), tanh_fast(h.y));
    }
}

extern "C" void kernel_launch(void* const* d_in, const int* in_sizes, int n_in,
                              void* d_out, int out_size) {
    const float* x  = (const float*)d_in[0];
    const float* W  = (const float*)d_in[1];
    const float* bv = (const float*)d_in[2];
    float* out = (float*)d_out;

    winattn_kernel<<<2 * Sdim, NTH>>>(x, W, bv, out);
}

// round 13
// speedup vs baseline: 1.5379x; 1.0497x over previous
#include <cuda_runtime.h>
#include <math.h>

#define Sdim 2048
#define Edim 512
#define WIN  11
#define Fdim 5632            // WIN * Edim
#define NTH  128

// Packed dual-fp32 FMA: a.{x,y} += {xlo,xhi} * w   (w broadcast to both lanes)
__device__ __forceinline__ void ffma2(float2& a, float xlo, float xhi, float w) {
    asm("{\n\t.reg .b64 X, Wd, A;\n\t"
        "mov.b64 X, {%2, %3};\n\t"
        "mov.b64 Wd, {%4, %4};\n\t"
        "mov.b64 A, {%0, %1};\n\t"
        "fma.rn.f32x2 A, X, Wd, A;\n\t"
        "mov.b64 {%0, %1}, A;\n\t}"
        : "+f"(a.x), "+f"(a.y) : "f"(xlo), "f"(xhi), "f"(w));
}

__device__ __forceinline__ float tanh_fast(float v) {
    float r;
    asm("tanh.approx.f32 %0, %1;" : "=f"(r) : "f"(v));
    return r;
}

__device__ __forceinline__ void pf_l2(const void* p) {
    asm volatile("prefetch.global.L2 [%0];" :: "l"(p));
}

__device__ __forceinline__ void fma_block(float2 acc0[WIN], float2 acc1[WIN],
                                          const float4 w4[WIN],
                                          float4 xv0, float4 xv1, float4 xv2, float4 xv3) {
    #pragma unroll
    for (int w = 0; w < WIN; w++) {
        ffma2(acc0[w], xv0.x, xv1.x, w4[w].x);
        ffma2(acc0[w], xv0.y, xv1.y, w4[w].y);
        ffma2(acc0[w], xv0.z, xv1.z, w4[w].z);
        ffma2(acc0[w], xv0.w, xv1.w, w4[w].w);
        ffma2(acc1[w], xv2.x, xv3.x, w4[w].x);
        ffma2(acc1[w], xv2.y, xv3.y, w4[w].y);
        ffma2(acc1[w], xv2.z, xv3.z, w4[w].z);
        ffma2(acc1[w], xv2.w, xv3.w, w4[w].w);
    }
}

__global__ __launch_bounds__(NTH, 4)
void winattn_kernel(const float* __restrict__ x,
                    const float* __restrict__ W,
                    const float* __restrict__ bias,
                    float* __restrict__ out) {
    __shared__ float2 red[4][22];      // per-warp partials (2 local pairs x 11 w)
    __shared__ float2 gates[22];       // gates for this CTA's 4 batches

    const int s   = blockIdx.x >> 1;
    const int b0  = (blockIdx.x & 1) * 4;   // batches b0..b0+3
    const int tid = threadIdx.x;
    const int ex  = 4 * tid;                // float4 slot within e (0..508)

    const size_t bst = (size_t)Sdim * Edim;
    const float* Wb  = W + (size_t)s * (WIN * Fdim) + ex;
    const float* xb  = x + (size_t)b0 * bst + ex;
    const float* xr0 = xb + (size_t)(s - 5) * Edim;   // window start row (batch b0)
    const float* xr2 = xr0 + 2 * bst;                 // same row, batch b0+2
    const bool interior = (s >= 5) && (s <= Sdim - 6);

    // ---------------- Stage A: full-f gate dots for 4 batches --------------
    float2 acc[2][WIN];
    #pragma unroll
    for (int p = 0; p < 2; p++)
        #pragma unroll
        for (int w = 0; w < WIN; w++)
            acc[p][w] = make_float2(0.f, 0.f);

    if (interior) {
        #pragma unroll
        for (int i = 0; i < WIN; i++) {
            // prefetch W rows for iteration i+2 (fire-and-forget, no regs)
            if (i + 2 < WIN) {
                #pragma unroll
                for (int w = 0; w < WIN; w++)
                    pf_l2(Wb + (size_t)w * Fdim + (i + 2) * Edim);
            }
            float4 w4[WIN];
            #pragma unroll
            for (int w = 0; w < WIN; w++)
                w4[w] = *(const float4*)(Wb + (size_t)w * Fdim + i * Edim);
            float4 xv0 = *(const float4*)(xr0 + i * Edim);
            float4 xv1 = *(const float4*)(xr0 + i * Edim + bst);
            float4 xv2 = *(const float4*)(xr2 + i * Edim);
            float4 xv3 = *(const float4*)(xr2 + i * Edim + bst);
            fma_block(acc[0], acc[1], w4, xv0, xv1, xv2, xv3);
        }
    } else {
        for (int i = 0; i < WIN; i++) {
            int row = s + i - 5;
            if ((unsigned)row >= (unsigned)Sdim) continue;
            float4 w4[WIN];
            #pragma unroll
            for (int w = 0; w < WIN; w++)
                w4[w] = *(const float4*)(Wb + (size_t)w * Fdim + i * Edim);
            const float* xr = xb + (size_t)row * Edim;
            float4 xv0 = *(const float4*)(xr);
            float4 xv1 = *(const float4*)(xr + bst);
            float4 xv2 = *(const float4*)(xr + 2 * bst);
            float4 xv3 = *(const float4*)(xr + 3 * bst);
            fma_block(acc[0], acc[1], w4, xv0, xv1, xv2, xv3);
        }
    }

    // ---------------- reduce: warp shfl, then 4 warps via smem -------------
    float* af = (float*)acc;           // 44 floats
    #pragma unroll
    for (int off = 16; off > 0; off >>= 1) {
        #pragma unroll
        for (int i = 0; i < 44; i++)
            af[i] += __shfl_xor_sync(0xffffffffu, af[i], off);
    }
    const int lane = tid & 31, wrp = tid >> 5;
    if (lane == 0) {
        #pragma unroll
        for (int p = 0; p < 2; p++)
            #pragma unroll
            for (int w = 0; w < WIN; w++)
                red[wrp][p * WIN + w] = acc[p][w];
    }
    __syncthreads();

    if (tid < 22) {
        int p = tid / WIN;             // local pair 0..1
        int w = tid - p * WIN;
        float2 t = make_float2(0.f, 0.f);
        #pragma unroll
        for (int q = 0; q < 4; q++) {
            float2 v = red[q][tid];
            t.x += v.x;
            t.y += v.y;
        }
        float bb = bias[s * WIN + w];
        float2 gt;
        gt.x = 1.0f / (1.0f + expf(-(t.x + bb)));
        gt.y = 1.0f / (1.0f + expf(-(t.y + bb)));
        gates[tid] = gt;               // .x = batch b0+2p, .y = batch b0+2p+1
    }
    __syncthreads();

    // ---------------- Stage B: score + tanh (x via L1/L2) ------------------
    float2 a[4][2];                    // [local batch][lo/hi float2 of float4]
    #pragma unroll
    for (int q = 0; q < 4; q++) {
        a[q][0] = make_float2(0.f, 0.f);
        a[q][1] = make_float2(0.f, 0.f);
    }

    if (interior) {
        #pragma unroll
        for (int w = 0; w < WIN; w++) {
            float4 xv0 = *(const float4*)(xr0 + w * Edim);
            float4 xv1 = *(const float4*)(xr0 + w * Edim + bst);
            float4 xv2 = *(const float4*)(xr2 + w * Edim);
            float4 xv3 = *(const float4*)(xr2 + w * Edim + bst);
            float2 g0 = gates[w];
            float2 g1 = gates[WIN + w];
            ffma2(a[0][0], xv0.x, xv0.y, g0.x);
            ffma2(a[0][1], xv0.z, xv0.w, g0.x);
            ffma2(a[1][0], xv1.x, xv1.y, g0.y);
            ffma2(a[1][1], xv1.z, xv1.w, g0.y);
            ffma2(a[2][0], xv2.x, xv2.y, g1.x);
            ffma2(a[2][1], xv2.z, xv2.w, g1.x);
            ffma2(a[3][0], xv3.x, xv3.y, g1.y);
            ffma2(a[3][1], xv3.z, xv3.w, g1.y);
        }
    } else {
        for (int w = 0; w < WIN; w++) {
            int row = s + w - 5;
            if ((unsigned)row >= (unsigned)Sdim) continue;
            const float* xr = xb + (size_t)row * Edim;
            #pragma unroll
            for (int q = 0; q < 4; q++) {
                float4 xv = *(const float4*)(xr + (size_t)q * bst);
                float2 gp = gates[(q >> 1) * WIN + w];
                float g = (q & 1) ? gp.y : gp.x;
                ffma2(a[q][0], xv.x, xv.y, g);
                ffma2(a[q][1], xv.z, xv.w, g);
            }
        }
    }

    #pragma unroll
    for (int q = 0; q < 4; q++) {
        float4 o;
        o.x = tanh_fast(a[q][0].x);
        o.y = tanh_fast(a[q][0].y);
        o.z = tanh_fast(a[q][1].x);
        o.w = tanh_fast(a[q][1].y);
        *(float4*)(out + ((size_t)(b0 + q) * Sdim + s) * Edim + ex) = o;
    }
}

extern "C" void kernel_launch(void* const* d_in, const int* in_sizes, int n_in,
                              void* d_out, int out_size) {
    const float* x  = (const float*)d_in[0];
    const float* W  = (const float*)d_in[1];
    const float* bv = (const float*)d_in[2];
    float* out = (float*)d_out;

    winattn_kernel<<<2 * Sdim, NTH>>>(x, W, bv, out);
}